// round 8
// baseline (speedup 1.0000x reference)
#include <cuda_runtime.h>
#include <math.h>

// Problem shape (fixed by reference setup_inputs)
#define UU 2048
#define TT 512
#define QQ 10000
#define HH 128
#define UT (UU*TT)
#define CH 16          // scan: time steps per lane (32 lanes * 16 = 512)

#define TBLK 296       // table kernel blocks (~2/SM)
#define TITER 5        // 296*5*16 = 23680 >= 20000 pairs

// Scratch (device globals: allocation-free, graph-capturable)
__device__ float  g_diff[QQ];
__device__ float  g_disc[QQ];
__device__ float2 g_tab[2*QQ];       // (mu, lmda) per (q, resp)
__device__ float  g_W2t[HH*HH];      // W2 transposed: g_W2t[j*HH + k] = W2[k*HH + j]

typedef unsigned long long ull;

__device__ __forceinline__ float gelu_exact(float x) {
    return 0.5f * x * (1.0f + erff(x * 0.70710678118654752440f));
}
__device__ __forceinline__ ull pack2(float lo, float hi) {
    ull r; asm("mov.b64 %0, {%1, %2};" : "=l"(r) : "f"(lo), "f"(hi)); return r;
}
__device__ __forceinline__ void unpack2(ull v, float& lo, float& hi) {
    asm("mov.b64 {%0, %1}, %2;" : "=f"(lo), "=f"(hi) : "l"(v));
}
__device__ __forceinline__ ull fma2(ull a, ull b, ull c) {
    ull d; asm("fma.rn.f32x2 %0, %1, %2, %3;" : "=l"(d) : "l"(a), "l"(b), "l"(c)); return d;
}

// ---------------------------------------------------------------------------
// Kernel 0: transpose W2 (128x128) into g_W2t so channel-j weight stream is
// contiguous (enables LDG.128 in the table kernel's inner loop).
// ---------------------------------------------------------------------------
__global__ void transpose_kernel(const float* __restrict__ W2) {
    __shared__ float t[32][33];
    int x = threadIdx.x;
    for (int i = threadIdx.y; i < 32; i += 8)
        t[i][x] = W2[(blockIdx.y*32 + i)*HH + blockIdx.x*32 + x];
    __syncthreads();
    for (int i = threadIdx.y; i < 32; i += 8)
        g_W2t[(blockIdx.x*32 + i)*HH + blockIdx.y*32 + x] = t[x][i];
}

// ---------------------------------------------------------------------------
// Kernel 1 (fused sample + MLP table): resp in {0,1} -> only 2*QQ distinct
// MLP inputs. 256 threads/block, two 128-thread halves, each half processes
// 8 pairs (= 4 q's x 2 resp) per W2 pass. Layer-2 accumulators are packed
// across pair-lanes with fma.rn.f32x2 (halves FMA warp-instrs); weights come
// from the transposed copy via one LDG.128 per 4 k's; h operands are
// broadcast LDS.128 of pre-interleaved float2 pairs.
// ---------------------------------------------------------------------------
__global__ void __launch_bounds__(256) table_kernel(
        const float* __restrict__ dmu, const float* __restrict__ dlv,
        const float* __restrict__ cmu, const float* __restrict__ clv,
        const float* __restrict__ ed,  const float* __restrict__ ec,
        const float* __restrict__ W1, const float* __restrict__ b1,
        const float* __restrict__ b2,
        const float* __restrict__ W3, const float* __restrict__ b3) {
    const int tid  = threadIdx.x;
    const int half = tid >> 7;          // 0 or 1
    const int j    = tid & 127;         // channel
    const int wwarp = (tid >> 5) & 3;   // warp within half
    const int lane  = tid & 31;

    // ---- folded sample pass (first 40 blocks cover QQ) ----
    int gid = blockIdx.x * 256 + tid;
    if (gid < QQ) {
        g_diff[gid] = fmaf(expf(0.5f * dlv[gid]), ed[gid], dmu[gid]);
        g_disc[gid] = fmaf(expf(0.5f * clv[gid]), ec[gid], cmu[gid]);
    }

    // hp[half][g][k] = float2( h[2g][k], h[2g+1][k] ) : pair-interleaved
    __shared__ __align__(16) float2 hp[2][4][HH];
    __shared__ float s0[16][4], s1[16][4];

    const float w1a = W1[j];
    const float w1b = W1[HH + j];
    const float w1c = W1[2*HH + j];
    const float b1j = b1[j];
    const float b2j = b2[j];
    const float w3a = W3[2*j + 0];
    const float w3b = W3[2*j + 1];
    const float4* w2row = reinterpret_cast<const float4*>(g_W2t + j*HH);

    for (int it = 0; it < TITER; ++it) {
        const int pbase = (blockIdx.x * TITER + it) * 16;  // 16 pairs/block/iter
        const int pb2   = (pbase >> 1) + half * 4;         // first q of this half

        // ---- layer 1: 4 q's x {resp=0, resp=1} ----
#pragma unroll
        for (int g = 0; g < 4; ++g) {
            int q = pb2 + g;
            float td = 0.f, tc = 0.f;
            if (q < QQ) {
                td = fmaf(expf(0.5f * __ldg(&dlv[q])), __ldg(&ed[q]), __ldg(&dmu[q]));
                tc = fmaf(expf(0.5f * __ldg(&clv[q])), __ldg(&ec[q]), __ldg(&cmu[q]));
            }
            float pre0 = fmaf(td, w1a, fmaf(tc, w1b, b1j));   // resp = 0
            float pre1 = pre0 + w1c;                          // resp = 1
            hp[half][g][j] = make_float2(gelu_exact(pre0), gelu_exact(pre1));
        }
        __syncthreads();

        // ---- layer 2: packed-pair accumulation, one W2 pass for 8 pairs ----
        ull acc0 = pack2(b2j, b2j), acc1 = acc0, acc2 = acc0, acc3 = acc0;
        const ulonglong2* h0 = reinterpret_cast<const ulonglong2*>(hp[half][0]);
        const ulonglong2* h1 = reinterpret_cast<const ulonglong2*>(hp[half][1]);
        const ulonglong2* h2 = reinterpret_cast<const ulonglong2*>(hp[half][2]);
        const ulonglong2* h3 = reinterpret_cast<const ulonglong2*>(hp[half][3]);
#pragma unroll 8
        for (int kc = 0; kc < 32; ++kc) {
            float4 wv = __ldg(&w2row[kc]);                 // W2t[j][4kc..4kc+3]
            ull wq0 = pack2(wv.x, wv.x);
            ull wq1 = pack2(wv.y, wv.y);
            ull wq2 = pack2(wv.z, wv.z);
            ull wq3 = pack2(wv.w, wv.w);
            ulonglong2 a0 = h0[2*kc], b0 = h0[2*kc+1];     // k..k+1, k+2..k+3
            ulonglong2 a1 = h1[2*kc], b1v = h1[2*kc+1];
            ulonglong2 a2 = h2[2*kc], b2v = h2[2*kc+1];
            ulonglong2 a3 = h3[2*kc], b3v = h3[2*kc+1];
            acc0 = fma2(a0.x, wq0, acc0); acc0 = fma2(a0.y, wq1, acc0);
            acc0 = fma2(b0.x, wq2, acc0); acc0 = fma2(b0.y, wq3, acc0);
            acc1 = fma2(a1.x, wq0, acc1); acc1 = fma2(a1.y, wq1, acc1);
            acc1 = fma2(b1v.x, wq2, acc1); acc1 = fma2(b1v.y, wq3, acc1);
            acc2 = fma2(a2.x, wq0, acc2); acc2 = fma2(a2.y, wq1, acc2);
            acc2 = fma2(b2v.x, wq2, acc2); acc2 = fma2(b2v.y, wq3, acc2);
            acc3 = fma2(a3.x, wq0, acc3); acc3 = fma2(a3.y, wq1, acc3);
            acc3 = fma2(b3v.x, wq2, acc3); acc3 = fma2(b3v.y, wq3, acc3);
        }

        // ---- layer 3 + warp reduction, 8 pairs ----
        float h2o[8];
        unpack2(acc0, h2o[0], h2o[1]);
        unpack2(acc1, h2o[2], h2o[3]);
        unpack2(acc2, h2o[4], h2o[5]);
        unpack2(acc3, h2o[6], h2o[7]);
#pragma unroll
        for (int p = 0; p < 8; ++p) {
            float hv = gelu_exact(h2o[p]);
            float m0 = hv * w3a;
            float m1 = hv * w3b;
#pragma unroll
            for (int off = 16; off; off >>= 1) {
                m0 += __shfl_down_sync(0xffffffffu, m0, off);
                m1 += __shfl_down_sync(0xffffffffu, m1, off);
            }
            if (lane == 0) { s0[half*8 + p][wwarp] = m0; s1[half*8 + p][wwarp] = m1; }
        }
        __syncthreads();

        if (tid < 16) {
            int pair = pbase + tid;
            if (pair < 2*QQ) {
                float mu = __ldg(&b3[0]) + ((s0[tid][0] + s0[tid][1]) + (s0[tid][2] + s0[tid][3]));
                float p1 = __ldg(&b3[1]) + ((s1[tid][0] + s1[tid][1]) + (s1[tid][2] + s1[tid][3]));
                g_tab[pair] = make_float2(mu, fminf(expf(-p1), 1e32f));
            }
        }
        __syncthreads();
    }
}

// ---------------------------------------------------------------------------
// Kernel 2 (fused): per-user backward + forward scans via chunked warp scans.
// One warp per user (4 users / 128-thread block); lane k owns t in [16k,16k+16).
// Backward step matrix (homogeneous (p,q,w), a=p/q, ab=a*b=w/q):
//   [[1,l,0],[1,1+l,0],[0,lm,1]]; the forgetting factor WC multiplies the
//   older composite's w-row during composition. Forward pass is affine.
// ---------------------------------------------------------------------------
__global__ void fused_scan_kernel(
        const int*   __restrict__ mask,
        const int*   __restrict__ q_id,
        const float* __restrict__ resp,
        const float* __restrict__ eps_ab,
        float*       __restrict__ out) {
    const int u = blockIdx.x * 4 + (threadIdx.x >> 5);
    const int k = threadIdx.x & 31;
    const int base = u * TT + k * CH;

    int4   mk4[4], q4[4];
    float4 r4[4], e4[4];
#pragma unroll
    for (int i = 0; i < 4; ++i) {
        mk4[i] = reinterpret_cast<const int4*>(mask + base)[i];
        q4[i]  = reinterpret_cast<const int4*>(q_id + base)[i];
        r4[i]  = reinterpret_cast<const float4*>(resp + base)[i];
        e4[i]  = reinterpret_cast<const float4*>(eps_ab + base)[i];
    }
    const int*   mk = reinterpret_cast<const int*>(mk4);
    const int*   qq = reinterpret_cast<const int*>(q4);
    const float* rr = reinterpret_cast<const float*>(r4);
    const float* ee = reinterpret_cast<const float*>(e4);

    float l[CH], lm[CH];
    bool  up[CH];
#pragma unroll
    for (int i = 0; i < CH; ++i) {
        int q = qq[i];
        int r = (rr[i] > 0.5f) ? 1 : 0;
        float2 ml = g_tab[(q << 1) | r];
        l[i]  = ml.y;
        lm[i] = ml.y * ml.x;
        up[i] = (mk[i] != 0);
    }

    // ---- backward: per-lane chunk matrix ----
    float A11 = 1.f, A12 = 0.f, A21 = 0.f, A22 = 1.f;
    float C1 = 0.f, C2 = 0.f, WC = 1.f;
#pragma unroll
    for (int i = CH - 1; i >= 0; --i) {
        if (up[i]) {
            float li = l[i];
            float s  = __fdividef(1.0f, 1.0f + li);
            float n11 = (A11 + li * A21) * s;
            float n12 = (A12 + li * A22) * s;
            float n21 = n11 + A21 * s;
            float n22 = n12 + A22 * s;
            float nc1 = fmaf(lm[i], A21, C1) * s;
            float nc2 = fmaf(lm[i], A22, C2) * s;
            A11 = n11; A12 = n12; A21 = n21; A22 = n22;
            C1 = nc1; C2 = nc2; WC *= s;
        }
    }
    {
        float s = __fdividef(1.0f, A22);
        A11 *= s; A12 *= s; A21 *= s; A22 *= s;
        C1 *= s; C2 *= s; WC *= s;
    }

    // ---- warp suffix scan (Z = A*Y; w-row: zc = C*y + WC*yc) ----
#pragma unroll
    for (int off = 1; off < 32; off <<= 1) {
        float y11 = __shfl_down_sync(0xffffffffu, A11, off);
        float y12 = __shfl_down_sync(0xffffffffu, A12, off);
        float y21 = __shfl_down_sync(0xffffffffu, A21, off);
        float y22 = __shfl_down_sync(0xffffffffu, A22, off);
        float yc1 = __shfl_down_sync(0xffffffffu, C1,  off);
        float yc2 = __shfl_down_sync(0xffffffffu, C2,  off);
        float ywc = __shfl_down_sync(0xffffffffu, WC,  off);
        if (k + off < 32) {
            float z11 = fmaf(A11, y11, A12 * y21);
            float z12 = fmaf(A11, y12, A12 * y22);
            float z21 = fmaf(A21, y11, A22 * y21);
            float z22 = fmaf(A21, y12, A22 * y22);
            float zc1 = fmaf(C1, y11, fmaf(C2, y21, WC * yc1));
            float zc2 = fmaf(C1, y12, fmaf(C2, y22, WC * yc2));
            float zwc = WC * ywc;
            float s = __fdividef(1.0f, z22);
            A11 = z11 * s; A12 = z12 * s; A21 = z21 * s; A22 = z22 * s;
            C1 = zc1 * s;  C2 = zc2 * s;  WC = zwc * s;
        }
    }
    float E12 = __shfl_down_sync(0xffffffffu, A12, 1);
    float E22 = __shfl_down_sync(0xffffffffu, A22, 1);
    float Ec2 = __shfl_down_sync(0xffffffffu, C2,  1);
    if (k == 31) { E12 = 0.f; E22 = 1.f; Ec2 = 0.f; }
    float a  = E12 / E22;
    float ab = Ec2 / E22;

    // ---- backward replay in (a, ab): PRE-update per t ----
    float an[CH], abn[CH];
#pragma unroll
    for (int i = CH - 1; i >= 0; --i) {
        an[i] = a; abn[i] = ab;
        if (up[i]) {
            float d   = l[i] + a;
            float num = lm[i] + ab;
            float s   = __fdividef(1.0f, 1.0f + d);
            a  = d * s;
            ab = num * s;
        }
    }

    // ---- forward: per-lane affine compose ----
    float inv[CH], bet[CH];
    float alC = 1.f, beC = 0.f;
#pragma unroll
    for (int i = 0; i < CH; ++i) {
        if (up[i]) {
            float iv = __fdividef(1.0f, 1.0f + l[i] + an[i]);
            float g  = (lm[i] + abn[i]) * iv;
            float bt = fmaf(sqrtf(fmaxf(0.0f, 1.0f - an[i])), ee[i], g);
            inv[i] = iv; bet[i] = bt;
            beC = fmaf(iv, beC, bt);
            alC *= iv;
        } else {
            inv[i] = 1.0f; bet[i] = 0.0f;
        }
    }

    // ---- warp prefix scan of affine pairs ----
#pragma unroll
    for (int off = 1; off < 32; off <<= 1) {
        float ya = __shfl_up_sync(0xffffffffu, alC, off);
        float yb = __shfl_up_sync(0xffffffffu, beC, off);
        if (k >= off) {
            beC = fmaf(alC, yb, beC);
            alC *= ya;
        }
    }
    float th = __shfl_up_sync(0xffffffffu, beC, 1);
    if (k == 0) th = 0.f;

    // ---- forward replay + streaming float4 outputs ----
#pragma unroll
    for (int g = 0; g < 4; ++g) {
        float4 lof, aof;
#pragma unroll
        for (int s = 0; s < 4; ++s) {
            int i = 4*g + s;
            if (up[i]) th = fmaf(th, inv[i], bet[i]);
            int q = qq[i];
            float dc = g_disc[q];
            float lv = dc * (th - g_diff[q]);
            if (s == 0) { lof.x = lv; aof.x = th; }
            else if (s == 1) { lof.y = lv; aof.y = th; }
            else if (s == 2) { lof.z = lv; aof.z = th; }
            else { lof.w = lv; aof.w = th; }
        }
        reinterpret_cast<float4*>(out + base)[g] = lof;
        reinterpret_cast<float4*>(out + UT + base)[g] = aof;
    }
}

// ---------------------------------------------------------------------------
// Launch
// ---------------------------------------------------------------------------
extern "C" void kernel_launch(void* const* d_in, const int* in_sizes, int n_in,
                              void* d_out, int out_size) {
    const int*   mask   = (const int*)  d_in[0];
    const int*   q_id   = (const int*)  d_in[1];
    const float* resp   = (const float*)d_in[2];
    const float* dmu    = (const float*)d_in[3];
    const float* dlv    = (const float*)d_in[4];
    const float* cmu    = (const float*)d_in[5];
    const float* clv    = (const float*)d_in[6];
    const float* W1     = (const float*)d_in[7];
    const float* b1     = (const float*)d_in[8];
    const float* W2     = (const float*)d_in[9];
    const float* b2     = (const float*)d_in[10];
    const float* W3     = (const float*)d_in[11];
    const float* b3     = (const float*)d_in[12];
    const float* ed     = (const float*)d_in[13];
    const float* ec     = (const float*)d_in[14];
    const float* eps_ab = (const float*)d_in[15];
    float* out = (float*)d_out;

    transpose_kernel<<<dim3(4, 4), dim3(32, 8)>>>(W2);
    table_kernel<<<TBLK, 256>>>(dmu, dlv, cmu, clv, ed, ec,
                                W1, b1, b2, W3, b3);
    fused_scan_kernel<<<UU / 4, 128>>>(mask, q_id, resp, eps_ab, out);
}

// round 9
// speedup vs baseline: 1.4466x; 1.4466x over previous
#include <cuda_runtime.h>
#include <math.h>

// Problem shape (fixed by reference setup_inputs)
#define UU 2048
#define TT 512
#define QQ 10000
#define HH 128
#define UT (UU*TT)
#define CH 16          // scan: time steps per lane (32 lanes * 16 = 512)

#define TBLK 296       // table kernel blocks (2/SM)
#define TITER 9        // 296*9*8 = 21312 >= 20000 pairs

// Scratch (device globals: allocation-free, graph-capturable)
__device__ float  g_diff[QQ];
__device__ float  g_disc[QQ];
__device__ float2 g_tab[2*QQ];     // (mu, lmda) per (q, resp)

__device__ __forceinline__ float gelu_exact(float x) {
    return 0.5f * x * (1.0f + erff(x * 0.70710678118654752440f));
}

// ---------------------------------------------------------------------------
// Kernel 1 (fused sample + MLP table): resp = round(uniform) in {0,1}, so the
// MLP has only 2*QQ distinct inputs. 256 threads/block, two 128-thread halves
// x 4 pairs each per iteration, register-blocked layer 2 (each W2 element
// loaded once per 4 pairs). Epilogue uses a multi-value butterfly reduction
// (9 shuffles for all 8 per-warp outputs instead of 80).
// ---------------------------------------------------------------------------
__global__ void __launch_bounds__(256) table_kernel(
        const float* __restrict__ dmu, const float* __restrict__ dlv,
        const float* __restrict__ cmu, const float* __restrict__ clv,
        const float* __restrict__ ed,  const float* __restrict__ ec,
        const float* __restrict__ W1, const float* __restrict__ b1,
        const float* __restrict__ W2, const float* __restrict__ b2,
        const float* __restrict__ W3, const float* __restrict__ b3) {
    const int tid  = threadIdx.x;
    const int half = tid >> 7;          // 0 or 1
    const int j    = tid & 127;         // channel
    const int wwarp = (tid >> 5) & 3;   // warp within half
    const int lane  = tid & 31;

    // ---- folded sample pass (first 40 blocks cover QQ) ----
    int gid = blockIdx.x * 256 + tid;
    if (gid < QQ) {
        g_diff[gid] = fmaf(__expf(0.5f * dlv[gid]), ed[gid], dmu[gid]);
        g_disc[gid] = fmaf(__expf(0.5f * clv[gid]), ec[gid], cmu[gid]);
    }

    __shared__ __align__(16) float h1s[8][HH];
    __shared__ float s_red[8][2][4];    // [pair-in-block][comp][warp]

    const float w1a = __ldg(&W1[j]);
    const float w1b = __ldg(&W1[HH + j]);
    const float w1c = __ldg(&W1[2*HH + j]);
    const float b1j = __ldg(&b1[j]);
    const float b2j = __ldg(&b2[j]);
    const float w3a = __ldg(&W3[2*j + 0]);
    const float w3b = __ldg(&W3[2*j + 1]);
    const float b30 = __ldg(&b3[0]);
    const float b31 = __ldg(&b3[1]);

    for (int it = 0; it < TITER; ++it) {
        int pbase = (blockIdx.x * TITER + it) * 8;   // first pair of this iter

        // ---- layer 1 for this half's 4 pairs ----
#pragma unroll
        for (int p = 0; p < 4; ++p) {
            int pair = pbase + half * 4 + p;
            float td = 0.f, tc = 0.f, rr = 0.f;
            if (pair < 2*QQ) {
                int q = pair >> 1;
                rr = (float)(pair & 1);
                td = fmaf(__expf(0.5f * __ldg(&dlv[q])), __ldg(&ed[q]), __ldg(&dmu[q]));
                tc = fmaf(__expf(0.5f * __ldg(&clv[q])), __ldg(&ec[q]), __ldg(&cmu[q]));
            }
            float pre = fmaf(td, w1a, fmaf(tc, w1b, fmaf(rr, w1c, b1j)));
            h1s[half*4 + p][j] = gelu_exact(pre);
        }
        __syncthreads();

        // ---- layer 2: register-blocked over this half's 4 pairs ----
        float acc0 = b2j, acc1 = b2j, acc2 = b2j, acc3 = b2j;
        const float* h0 = h1s[half*4 + 0];
        const float* h1 = h1s[half*4 + 1];
        const float* h2p = h1s[half*4 + 2];
        const float* h3 = h1s[half*4 + 3];
#pragma unroll 8
        for (int k = 0; k < HH; k += 4) {
            float w0 = __ldg(&W2[(k+0)*HH + j]);
            float w1 = __ldg(&W2[(k+1)*HH + j]);
            float w2 = __ldg(&W2[(k+2)*HH + j]);
            float w3 = __ldg(&W2[(k+3)*HH + j]);
            float4 v0 = *reinterpret_cast<const float4*>(&h0[k]);
            float4 v1 = *reinterpret_cast<const float4*>(&h1[k]);
            float4 v2 = *reinterpret_cast<const float4*>(&h2p[k]);
            float4 v3 = *reinterpret_cast<const float4*>(&h3[k]);
            acc0 = fmaf(v0.x, w0, fmaf(v0.y, w1, fmaf(v0.z, w2, fmaf(v0.w, w3, acc0))));
            acc1 = fmaf(v1.x, w0, fmaf(v1.y, w1, fmaf(v1.z, w2, fmaf(v1.w, w3, acc1))));
            acc2 = fmaf(v2.x, w0, fmaf(v2.y, w1, fmaf(v2.z, w2, fmaf(v2.w, w3, acc2))));
            acc3 = fmaf(v3.x, w0, fmaf(v3.y, w1, fmaf(v3.z, w2, fmaf(v3.w, w3, acc3))));
        }

        // ---- layer 3: 8 values per lane (4 pairs x {m0,m1}) ----
        // val[i], i = p*2 + c : p = pair-in-half, c = output component.
        float val[8];
        {
            float hh0 = gelu_exact(acc0), hh1 = gelu_exact(acc1);
            float hh2 = gelu_exact(acc2), hh3 = gelu_exact(acc3);
            val[0] = hh0 * w3a; val[1] = hh0 * w3b;
            val[2] = hh1 * w3a; val[3] = hh1 * w3b;
            val[4] = hh2 * w3a; val[5] = hh2 * w3b;
            val[6] = hh3 * w3a; val[7] = hh3 * w3b;
        }
        // Multi-value butterfly: each stage keeps half the values, exchanges
        // the other half. After stages o=16,8,4, lane L owns value (L>>2)&7;
        // stages o=2,1 complete the 32-lane sum (9 shuffles total).
        {
            bool b16 = (lane & 16) != 0;
#pragma unroll
            for (int i = 0; i < 4; ++i) {
                float send = b16 ? val[i] : val[4+i];
                float r = __shfl_xor_sync(0xffffffffu, send, 16);
                val[i] = (b16 ? val[4+i] : val[i]) + r;
            }
            bool b8 = (lane & 8) != 0;
#pragma unroll
            for (int i = 0; i < 2; ++i) {
                float send = b8 ? val[i] : val[2+i];
                float r = __shfl_xor_sync(0xffffffffu, send, 8);
                val[i] = (b8 ? val[2+i] : val[i]) + r;
            }
            bool b4 = (lane & 4) != 0;
            {
                float send = b4 ? val[0] : val[1];
                float r = __shfl_xor_sync(0xffffffffu, send, 4);
                val[0] = (b4 ? val[1] : val[0]) + r;
            }
            val[0] += __shfl_xor_sync(0xffffffffu, val[0], 2);
            val[0] += __shfl_xor_sync(0xffffffffu, val[0], 1);
        }
        if ((lane & 3) == 0) {
            int v = lane >> 2;              // owned value index 0..7
            s_red[half*4 + (v >> 1)][v & 1][wwarp] = val[0];
        }
        __syncthreads();

        if (tid < 8) {                      // one thread finalizes each pair
            int pair = pbase + tid;
            if (pair < 2*QQ) {
                float mu = b30 + ((s_red[tid][0][0] + s_red[tid][0][1])
                                + (s_red[tid][0][2] + s_red[tid][0][3]));
                float p1 = b31 + ((s_red[tid][1][0] + s_red[tid][1][1])
                                + (s_red[tid][1][2] + s_red[tid][1][3]));
                g_tab[pair] = make_float2(mu, fminf(__expf(-p1), 1e32f));
            }
        }
        __syncthreads();
    }
}

// ---------------------------------------------------------------------------
// Kernel 2 (fused): per-user backward + forward scans via chunked warp scans.
// One warp per user (4 users / 128-thread block); lane k owns t in [16k,16k+16).
// Backward step matrix (homogeneous (p,q,w), a=p/q, ab=a*b=w/q):
//   [[1,l,0],[1,1+l,0],[0,lm,1]]; the forgetting factor WC multiplies the
//   older composite's w-row during composition. Forward pass is affine.
// ---------------------------------------------------------------------------
__global__ void fused_scan_kernel(
        const int*   __restrict__ mask,
        const int*   __restrict__ q_id,
        const float* __restrict__ resp,
        const float* __restrict__ eps_ab,
        float*       __restrict__ out) {
    const int u = blockIdx.x * 4 + (threadIdx.x >> 5);
    const int k = threadIdx.x & 31;
    const int base = u * TT + k * CH;

    int4   mk4[4], q4[4];
    float4 r4[4], e4[4];
#pragma unroll
    for (int i = 0; i < 4; ++i) {
        mk4[i] = reinterpret_cast<const int4*>(mask + base)[i];
        q4[i]  = reinterpret_cast<const int4*>(q_id + base)[i];
        r4[i]  = reinterpret_cast<const float4*>(resp + base)[i];
        e4[i]  = reinterpret_cast<const float4*>(eps_ab + base)[i];
    }
    const int*   mk = reinterpret_cast<const int*>(mk4);
    const int*   qq = reinterpret_cast<const int*>(q4);
    const float* rr = reinterpret_cast<const float*>(r4);
    const float* ee = reinterpret_cast<const float*>(e4);

    float l[CH], lm[CH];
    bool  up[CH];
#pragma unroll
    for (int i = 0; i < CH; ++i) {
        int q = qq[i];
        int r = (rr[i] > 0.5f) ? 1 : 0;
        float2 ml = g_tab[(q << 1) | r];
        l[i]  = ml.y;
        lm[i] = ml.y * ml.x;
        up[i] = (mk[i] != 0);
    }

    // ---- backward: per-lane chunk matrix ----
    float A11 = 1.f, A12 = 0.f, A21 = 0.f, A22 = 1.f;
    float C1 = 0.f, C2 = 0.f, WC = 1.f;
#pragma unroll
    for (int i = CH - 1; i >= 0; --i) {
        if (up[i]) {
            float li = l[i];
            float s  = __fdividef(1.0f, 1.0f + li);
            float n11 = (A11 + li * A21) * s;
            float n12 = (A12 + li * A22) * s;
            float n21 = n11 + A21 * s;
            float n22 = n12 + A22 * s;
            float nc1 = fmaf(lm[i], A21, C1) * s;
            float nc2 = fmaf(lm[i], A22, C2) * s;
            A11 = n11; A12 = n12; A21 = n21; A22 = n22;
            C1 = nc1; C2 = nc2; WC *= s;
        }
    }
    {
        float s = __fdividef(1.0f, A22);
        A11 *= s; A12 *= s; A21 *= s; A22 *= s;
        C1 *= s; C2 *= s; WC *= s;
    }

    // ---- warp suffix scan (Z = A*Y; w-row: zc = C*y + WC*yc) ----
#pragma unroll
    for (int off = 1; off < 32; off <<= 1) {
        float y11 = __shfl_down_sync(0xffffffffu, A11, off);
        float y12 = __shfl_down_sync(0xffffffffu, A12, off);
        float y21 = __shfl_down_sync(0xffffffffu, A21, off);
        float y22 = __shfl_down_sync(0xffffffffu, A22, off);
        float yc1 = __shfl_down_sync(0xffffffffu, C1,  off);
        float yc2 = __shfl_down_sync(0xffffffffu, C2,  off);
        float ywc = __shfl_down_sync(0xffffffffu, WC,  off);
        if (k + off < 32) {
            float z11 = fmaf(A11, y11, A12 * y21);
            float z12 = fmaf(A11, y12, A12 * y22);
            float z21 = fmaf(A21, y11, A22 * y21);
            float z22 = fmaf(A21, y12, A22 * y22);
            float zc1 = fmaf(C1, y11, fmaf(C2, y21, WC * yc1));
            float zc2 = fmaf(C1, y12, fmaf(C2, y22, WC * yc2));
            float zwc = WC * ywc;
            float s = __fdividef(1.0f, z22);
            A11 = z11 * s; A12 = z12 * s; A21 = z21 * s; A22 = z22 * s;
            C1 = zc1 * s;  C2 = zc2 * s;  WC = zwc * s;
        }
    }
    float E12 = __shfl_down_sync(0xffffffffu, A12, 1);
    float E22 = __shfl_down_sync(0xffffffffu, A22, 1);
    float Ec2 = __shfl_down_sync(0xffffffffu, C2,  1);
    if (k == 31) { E12 = 0.f; E22 = 1.f; Ec2 = 0.f; }
    float a  = E12 / E22;
    float ab = Ec2 / E22;

    // ---- backward replay in (a, ab): PRE-update per t ----
    float an[CH], abn[CH];
#pragma unroll
    for (int i = CH - 1; i >= 0; --i) {
        an[i] = a; abn[i] = ab;
        if (up[i]) {
            float d   = l[i] + a;
            float num = lm[i] + ab;
            float s   = __fdividef(1.0f, 1.0f + d);
            a  = d * s;
            ab = num * s;
        }
    }

    // ---- forward: per-lane affine compose ----
    float inv[CH], bet[CH];
    float alC = 1.f, beC = 0.f;
#pragma unroll
    for (int i = 0; i < CH; ++i) {
        if (up[i]) {
            float iv = __fdividef(1.0f, 1.0f + l[i] + an[i]);
            float g  = (lm[i] + abn[i]) * iv;
            float bt = fmaf(sqrtf(fmaxf(0.0f, 1.0f - an[i])), ee[i], g);
            inv[i] = iv; bet[i] = bt;
            beC = fmaf(iv, beC, bt);
            alC *= iv;
        } else {
            inv[i] = 1.0f; bet[i] = 0.0f;
        }
    }

    // ---- warp prefix scan of affine pairs ----
#pragma unroll
    for (int off = 1; off < 32; off <<= 1) {
        float ya = __shfl_up_sync(0xffffffffu, alC, off);
        float yb = __shfl_up_sync(0xffffffffu, beC, off);
        if (k >= off) {
            beC = fmaf(alC, yb, beC);
            alC *= ya;
        }
    }
    float th = __shfl_up_sync(0xffffffffu, beC, 1);
    if (k == 0) th = 0.f;

    // ---- forward replay + streaming float4 outputs ----
#pragma unroll
    for (int g = 0; g < 4; ++g) {
        float4 lof, aof;
#pragma unroll
        for (int s = 0; s < 4; ++s) {
            int i = 4*g + s;
            if (up[i]) th = fmaf(th, inv[i], bet[i]);
            int q = qq[i];
            float dc = g_disc[q];
            float lv = dc * (th - g_diff[q]);
            if (s == 0) { lof.x = lv; aof.x = th; }
            else if (s == 1) { lof.y = lv; aof.y = th; }
            else if (s == 2) { lof.z = lv; aof.z = th; }
            else { lof.w = lv; aof.w = th; }
        }
        reinterpret_cast<float4*>(out + base)[g] = lof;
        reinterpret_cast<float4*>(out + UT + base)[g] = aof;
    }
}

// ---------------------------------------------------------------------------
// Launch
// ---------------------------------------------------------------------------
extern "C" void kernel_launch(void* const* d_in, const int* in_sizes, int n_in,
                              void* d_out, int out_size) {
    const int*   mask   = (const int*)  d_in[0];
    const int*   q_id   = (const int*)  d_in[1];
    const float* resp   = (const float*)d_in[2];
    const float* dmu    = (const float*)d_in[3];
    const float* dlv    = (const float*)d_in[4];
    const float* cmu    = (const float*)d_in[5];
    const float* clv    = (const float*)d_in[6];
    const float* W1     = (const float*)d_in[7];
    const float* b1     = (const float*)d_in[8];
    const float* W2     = (const float*)d_in[9];
    const float* b2     = (const float*)d_in[10];
    const float* W3     = (const float*)d_in[11];
    const float* b3     = (const float*)d_in[12];
    const float* ed     = (const float*)d_in[13];
    const float* ec     = (const float*)d_in[14];
    const float* eps_ab = (const float*)d_in[15];
    float* out = (float*)d_out;

    table_kernel<<<TBLK, 256>>>(dmu, dlv, cmu, clv, ed, ec,
                                W1, b1, W2, b2, W3, b3);
    fused_scan_kernel<<<UU / 4, 128>>>(mask, q_id, resp, eps_ab, out);
}

// round 11
// speedup vs baseline: 1.7759x; 1.2277x over previous
#include <cuda_runtime.h>
#include <math.h>

// Problem shape (fixed by reference setup_inputs)
#define UU 2048
#define TT 512
#define QQ 10000
#define HH 128
#define UT (UU*TT)
#define CH 16          // scan: time steps per lane (32 lanes * 16 = 512)

#define TBLK 296       // table kernel blocks (2/SM)
#define NCHUNK 1250    // 16-pair chunks: 1250*16 = 20000 exactly

// Scratch (device globals: allocation-free, graph-capturable)
__device__ float  g_diff[QQ];
__device__ float  g_disc[QQ];
__device__ float2 g_tab[2*QQ];     // (mu, lmda) per (q, resp)

__device__ __forceinline__ float gelu_exact(float x) {
    return 0.5f * x * (1.0f + erff(x * 0.70710678118654752440f));
}

// ---------------------------------------------------------------------------
// Kernel 1 (fused sample + MLP table): resp = round(uniform) in {0,1}, so the
// MLP has only 2*QQ distinct inputs. 256 threads/block, two 128-thread halves,
// each half computes 8 pairs (4 q x 2 resp) per W2 pass: every W2 element
// loaded once per 8 pairs -> 73% FFMA issue mix in the inner loop.
// Grid-strided over exactly NCHUNK chunks (no bounds guards, no waste).
// ---------------------------------------------------------------------------
__global__ void __launch_bounds__(256) table_kernel(
        const float* __restrict__ dmu, const float* __restrict__ dlv,
        const float* __restrict__ cmu, const float* __restrict__ clv,
        const float* __restrict__ ed,  const float* __restrict__ ec,
        const float* __restrict__ W1, const float* __restrict__ b1,
        const float* __restrict__ W2, const float* __restrict__ b2,
        const float* __restrict__ W3, const float* __restrict__ b3) {
    const int tid  = threadIdx.x;
    const int half = tid >> 7;          // 0 or 1
    const int j    = tid & 127;         // channel
    const int wwarp = (tid >> 5) & 3;   // warp within half
    const int lane  = tid & 31;

    // ---- folded sample pass (first 40 blocks cover QQ) ----
    int gid = blockIdx.x * 256 + tid;
    if (gid < QQ) {
        g_diff[gid] = fmaf(__expf(0.5f * dlv[gid]), ed[gid], dmu[gid]);
        g_disc[gid] = fmaf(__expf(0.5f * clv[gid]), ec[gid], cmu[gid]);
    }

    __shared__ __align__(16) float h1s[16][HH];   // 16 pairs per chunk
    __shared__ float s_red[16][2][4];             // [pair][comp][warp]

    const float w1a = __ldg(&W1[j]);
    const float w1b = __ldg(&W1[HH + j]);
    const float w1c = __ldg(&W1[2*HH + j]);
    const float b1j = __ldg(&b1[j]);
    const float b2j = __ldg(&b2[j]);
    const float w3a = __ldg(&W3[2*j + 0]);
    const float w3b = __ldg(&W3[2*j + 1]);
    const float b30 = __ldg(&b3[0]);
    const float b31 = __ldg(&b3[1]);

    for (int c = blockIdx.x; c < NCHUNK; c += TBLK) {
        const int pbase = c * 16;            // 16 pairs; all < 2*QQ by range
        const int qbase = c * 8 + half * 4;  // this half's 4 q's

        // ---- layer 1: 4 q's x {resp=0,1} -> 8 h rows for this half ----
#pragma unroll
        for (int g = 0; g < 4; ++g) {
            int q = qbase + g;
            float td = fmaf(__expf(0.5f * __ldg(&dlv[q])), __ldg(&ed[q]), __ldg(&dmu[q]));
            float tc = fmaf(__expf(0.5f * __ldg(&clv[q])), __ldg(&ec[q]), __ldg(&cmu[q]));
            float pre0 = fmaf(td, w1a, fmaf(tc, w1b, b1j));   // resp = 0
            float pre1 = pre0 + w1c;                          // resp = 1
            h1s[half*8 + 2*g + 0][j] = gelu_exact(pre0);
            h1s[half*8 + 2*g + 1][j] = gelu_exact(pre1);
        }
        __syncthreads();

        // ---- layer 2: one W2 pass feeds 8 accumulators ----
        float acc[8];
#pragma unroll
        for (int p = 0; p < 8; ++p) acc[p] = b2j;
#pragma unroll 4
        for (int kc = 0; kc < 32; ++kc) {
            int k = kc * 4;
            float w0 = __ldg(&W2[(k+0)*HH + j]);
            float w1 = __ldg(&W2[(k+1)*HH + j]);
            float w2 = __ldg(&W2[(k+2)*HH + j]);
            float w3 = __ldg(&W2[(k+3)*HH + j]);
#pragma unroll
            for (int p = 0; p < 8; ++p) {
                float4 v = *reinterpret_cast<const float4*>(&h1s[half*8 + p][k]);
                acc[p] = fmaf(v.x, w0, fmaf(v.y, w1, fmaf(v.z, w2, fmaf(v.w, w3, acc[p]))));
            }
        }

        // ---- layer 3: 16 values per lane (8 pairs x {m0,m1}) ----
        float val[16];
#pragma unroll
        for (int p = 0; p < 8; ++p) {
            float hv = gelu_exact(acc[p]);
            val[2*p + 0] = hv * w3a;
            val[2*p + 1] = hv * w3b;
        }
        // Multi-value butterfly: stages o=16,8,4,2 halve the value count
        // (keep-half/exchange-half); after them lane L owns value (L>>1)&15;
        // stage o=1 completes the 32-lane sum. 15 shuffles total.
        {
            bool b16 = (lane & 16) != 0;
#pragma unroll
            for (int i = 0; i < 8; ++i) {
                float send = b16 ? val[i] : val[8+i];
                float r = __shfl_xor_sync(0xffffffffu, send, 16);
                val[i] = (b16 ? val[8+i] : val[i]) + r;
            }
            bool b8 = (lane & 8) != 0;
#pragma unroll
            for (int i = 0; i < 4; ++i) {
                float send = b8 ? val[i] : val[4+i];
                float r = __shfl_xor_sync(0xffffffffu, send, 8);
                val[i] = (b8 ? val[4+i] : val[i]) + r;
            }
            bool b4 = (lane & 4) != 0;
#pragma unroll
            for (int i = 0; i < 2; ++i) {
                float send = b4 ? val[i] : val[2+i];
                float r = __shfl_xor_sync(0xffffffffu, send, 4);
                val[i] = (b4 ? val[2+i] : val[i]) + r;
            }
            bool b2v = (lane & 2) != 0;
            {
                float send = b2v ? val[0] : val[1];
                float r = __shfl_xor_sync(0xffffffffu, send, 2);
                val[0] = (b2v ? val[1] : val[0]) + r;
            }
            val[0] += __shfl_xor_sync(0xffffffffu, val[0], 1);
        }
        if ((lane & 1) == 0) {
            int v = (lane >> 1) & 15;       // owned value index: p*2 + comp
            s_red[half*8 + (v >> 1)][v & 1][wwarp] = val[0];
        }
        __syncthreads();

        if (tid < 16) {                     // one thread finalizes each pair
            int pair = pbase + tid;
            float mu = b30 + ((s_red[tid][0][0] + s_red[tid][0][1])
                            + (s_red[tid][0][2] + s_red[tid][0][3]));
            float p1 = b31 + ((s_red[tid][1][0] + s_red[tid][1][1])
                            + (s_red[tid][1][2] + s_red[tid][1][3]));
            g_tab[pair] = make_float2(mu, fminf(__expf(-p1), 1e32f));
        }
        __syncthreads();
    }
}

// ---------------------------------------------------------------------------
// Kernel 2 (fused): per-user backward + forward scans via chunked warp scans.
// One warp per user (4 users / 128-thread block); lane k owns t in [16k,16k+16).
// Backward step matrix (homogeneous (p,q,w), a=p/q, ab=a*b=w/q):
//   [[1,l,0],[1,1+l,0],[0,lm,1]]; the forgetting factor WC multiplies the
//   older composite's w-row during composition. Forward pass is affine.
// ---------------------------------------------------------------------------
__global__ void fused_scan_kernel(
        const int*   __restrict__ mask,
        const int*   __restrict__ q_id,
        const float* __restrict__ resp,
        const float* __restrict__ eps_ab,
        float*       __restrict__ out) {
    const int u = blockIdx.x * 4 + (threadIdx.x >> 5);
    const int k = threadIdx.x & 31;
    const int base = u * TT + k * CH;

    int4   mk4[4], q4[4];
    float4 r4[4], e4[4];
#pragma unroll
    for (int i = 0; i < 4; ++i) {
        mk4[i] = reinterpret_cast<const int4*>(mask + base)[i];
        q4[i]  = reinterpret_cast<const int4*>(q_id + base)[i];
        r4[i]  = reinterpret_cast<const float4*>(resp + base)[i];
        e4[i]  = reinterpret_cast<const float4*>(eps_ab + base)[i];
    }
    const int*   mk = reinterpret_cast<const int*>(mk4);
    const int*   qq = reinterpret_cast<const int*>(q4);
    const float* rr = reinterpret_cast<const float*>(r4);
    const float* ee = reinterpret_cast<const float*>(e4);

    float l[CH], lm[CH];
    bool  up[CH];
#pragma unroll
    for (int i = 0; i < CH; ++i) {
        int q = qq[i];
        int r = (rr[i] > 0.5f) ? 1 : 0;
        float2 ml = g_tab[(q << 1) | r];
        l[i]  = ml.y;
        lm[i] = ml.y * ml.x;
        up[i] = (mk[i] != 0);
    }

    // ---- backward: per-lane chunk matrix ----
    float A11 = 1.f, A12 = 0.f, A21 = 0.f, A22 = 1.f;
    float C1 = 0.f, C2 = 0.f, WC = 1.f;
#pragma unroll
    for (int i = CH - 1; i >= 0; --i) {
        if (up[i]) {
            float li = l[i];
            float s  = __fdividef(1.0f, 1.0f + li);
            float n11 = (A11 + li * A21) * s;
            float n12 = (A12 + li * A22) * s;
            float n21 = n11 + A21 * s;
            float n22 = n12 + A22 * s;
            float nc1 = fmaf(lm[i], A21, C1) * s;
            float nc2 = fmaf(lm[i], A22, C2) * s;
            A11 = n11; A12 = n12; A21 = n21; A22 = n22;
            C1 = nc1; C2 = nc2; WC *= s;
        }
    }
    {
        float s = __fdividef(1.0f, A22);
        A11 *= s; A12 *= s; A21 *= s; A22 *= s;
        C1 *= s; C2 *= s; WC *= s;
    }

    // ---- warp suffix scan (Z = A*Y; w-row: zc = C*y + WC*yc) ----
#pragma unroll
    for (int off = 1; off < 32; off <<= 1) {
        float y11 = __shfl_down_sync(0xffffffffu, A11, off);
        float y12 = __shfl_down_sync(0xffffffffu, A12, off);
        float y21 = __shfl_down_sync(0xffffffffu, A21, off);
        float y22 = __shfl_down_sync(0xffffffffu, A22, off);
        float yc1 = __shfl_down_sync(0xffffffffu, C1,  off);
        float yc2 = __shfl_down_sync(0xffffffffu, C2,  off);
        float ywc = __shfl_down_sync(0xffffffffu, WC,  off);
        if (k + off < 32) {
            float z11 = fmaf(A11, y11, A12 * y21);
            float z12 = fmaf(A11, y12, A12 * y22);
            float z21 = fmaf(A21, y11, A22 * y21);
            float z22 = fmaf(A21, y12, A22 * y22);
            float zc1 = fmaf(C1, y11, fmaf(C2, y21, WC * yc1));
            float zc2 = fmaf(C1, y12, fmaf(C2, y22, WC * yc2));
            float zwc = WC * ywc;
            float s = __fdividef(1.0f, z22);
            A11 = z11 * s; A12 = z12 * s; A21 = z21 * s; A22 = z22 * s;
            C1 = zc1 * s;  C2 = zc2 * s;  WC = zwc * s;
        }
    }
    float E12 = __shfl_down_sync(0xffffffffu, A12, 1);
    float E22 = __shfl_down_sync(0xffffffffu, A22, 1);
    float Ec2 = __shfl_down_sync(0xffffffffu, C2,  1);
    if (k == 31) { E12 = 0.f; E22 = 1.f; Ec2 = 0.f; }
    float a  = E12 / E22;
    float ab = Ec2 / E22;

    // ---- backward replay in (a, ab): PRE-update per t ----
    float an[CH], abn[CH];
#pragma unroll
    for (int i = CH - 1; i >= 0; --i) {
        an[i] = a; abn[i] = ab;
        if (up[i]) {
            float d   = l[i] + a;
            float num = lm[i] + ab;
            float s   = __fdividef(1.0f, 1.0f + d);
            a  = d * s;
            ab = num * s;
        }
    }

    // ---- forward: per-lane affine compose ----
    float inv[CH], bet[CH];
    float alC = 1.f, beC = 0.f;
#pragma unroll
    for (int i = 0; i < CH; ++i) {
        if (up[i]) {
            float iv = __fdividef(1.0f, 1.0f + l[i] + an[i]);
            float g  = (lm[i] + abn[i]) * iv;
            float bt = fmaf(sqrtf(fmaxf(0.0f, 1.0f - an[i])), ee[i], g);
            inv[i] = iv; bet[i] = bt;
            beC = fmaf(iv, beC, bt);
            alC *= iv;
        } else {
            inv[i] = 1.0f; bet[i] = 0.0f;
        }
    }

    // ---- warp prefix scan of affine pairs ----
#pragma unroll
    for (int off = 1; off < 32; off <<= 1) {
        float ya = __shfl_up_sync(0xffffffffu, alC, off);
        float yb = __shfl_up_sync(0xffffffffu, beC, off);
        if (k >= off) {
            beC = fmaf(alC, yb, beC);
            alC *= ya;
        }
    }
    float th = __shfl_up_sync(0xffffffffu, beC, 1);
    if (k == 0) th = 0.f;

    // ---- forward replay + streaming float4 outputs ----
#pragma unroll
    for (int g = 0; g < 4; ++g) {
        float4 lof, aof;
#pragma unroll
        for (int s = 0; s < 4; ++s) {
            int i = 4*g + s;
            if (up[i]) th = fmaf(th, inv[i], bet[i]);
            int q = qq[i];
            float dc = g_disc[q];
            float lv = dc * (th - g_diff[q]);
            if (s == 0) { lof.x = lv; aof.x = th; }
            else if (s == 1) { lof.y = lv; aof.y = th; }
            else if (s == 2) { lof.z = lv; aof.z = th; }
            else { lof.w = lv; aof.w = th; }
        }
        reinterpret_cast<float4*>(out + base)[g] = lof;
        reinterpret_cast<float4*>(out + UT + base)[g] = aof;
    }
}

// ---------------------------------------------------------------------------
// Launch
// ---------------------------------------------------------------------------
extern "C" void kernel_launch(void* const* d_in, const int* in_sizes, int n_in,
                              void* d_out, int out_size) {
    const int*   mask   = (const int*)  d_in[0];
    const int*   q_id   = (const int*)  d_in[1];
    const float* resp   = (const float*)d_in[2];
    const float* dmu    = (const float*)d_in[3];
    const float* dlv    = (const float*)d_in[4];
    const float* cmu    = (const float*)d_in[5];
    const float* clv    = (const float*)d_in[6];
    const float* W1     = (const float*)d_in[7];
    const float* b1     = (const float*)d_in[8];
    const float* W2     = (const float*)d_in[9];
    const float* b2     = (const float*)d_in[10];
    const float* W3     = (const float*)d_in[11];
    const float* b3     = (const float*)d_in[12];
    const float* ed     = (const float*)d_in[13];
    const float* ec     = (const float*)d_in[14];
    const float* eps_ab = (const float*)d_in[15];
    float* out = (float*)d_out;

    table_kernel<<<TBLK, 256>>>(dmu, dlv, cmu, clv, ed, ec,
                                W1, b1, W2, b2, W3, b3);
    fused_scan_kernel<<<UU / 4, 128>>>(mask, q_id, resp, eps_ab, out);
}

// round 12
// speedup vs baseline: 1.9284x; 1.0859x over previous
#include <cuda_runtime.h>
#include <math.h>

// Problem shape (fixed by reference setup_inputs)
#define UU 2048
#define TT 512
#define QQ 10000
#define HH 128
#define UT (UU*TT)
#define CH 16          // scan: time steps per lane (32 lanes * 16 = 512)

#define TBLK 592       // table kernel blocks (4/SM)
#define NCHUNK 1250    // 16-pair chunks: 1250*16 = 20000 exactly

// Scratch (device globals: allocation-free, graph-capturable)
__device__ float  g_diff[QQ];
__device__ float  g_disc[QQ];
__device__ float2 g_tab[2*QQ];     // (mu, lmda) per (q, resp)

__device__ __forceinline__ float gelu_exact(float x) {
    return 0.5f * x * (1.0f + erff(x * 0.70710678118654752440f));
}

// ---------------------------------------------------------------------------
// Kernel 1 (fused sample + MLP table): resp = round(uniform) in {0,1}, so the
// MLP has only 2*QQ distinct inputs. 256 threads/block, two 128-thread halves,
// each half computes 8 pairs (4 q x 2 resp) per W2 pass (73% FFMA issue mix).
// Grid-strided over exactly NCHUNK chunks; 4 blocks/SM for latency hiding.
// ---------------------------------------------------------------------------
__global__ void __launch_bounds__(256) table_kernel(
        const float* __restrict__ dmu, const float* __restrict__ dlv,
        const float* __restrict__ cmu, const float* __restrict__ clv,
        const float* __restrict__ ed,  const float* __restrict__ ec,
        const float* __restrict__ W1, const float* __restrict__ b1,
        const float* __restrict__ W2, const float* __restrict__ b2,
        const float* __restrict__ W3, const float* __restrict__ b3) {
    const int tid  = threadIdx.x;
    const int half = tid >> 7;          // 0 or 1
    const int j    = tid & 127;         // channel
    const int wwarp = (tid >> 5) & 3;   // warp within half
    const int lane  = tid & 31;

    // ---- folded sample pass (first 40 blocks cover QQ) ----
    int gid = blockIdx.x * 256 + tid;
    if (gid < QQ) {
        g_diff[gid] = fmaf(__expf(0.5f * dlv[gid]), ed[gid], dmu[gid]);
        g_disc[gid] = fmaf(__expf(0.5f * clv[gid]), ec[gid], cmu[gid]);
    }

    __shared__ __align__(16) float h1s[16][HH];   // 16 pairs per chunk
    __shared__ float s_red[16][2][4];             // [pair][comp][warp]

    const float w1a = __ldg(&W1[j]);
    const float w1b = __ldg(&W1[HH + j]);
    const float w1c = __ldg(&W1[2*HH + j]);
    const float b1j = __ldg(&b1[j]);
    const float b2j = __ldg(&b2[j]);
    const float w3a = __ldg(&W3[2*j + 0]);
    const float w3b = __ldg(&W3[2*j + 1]);
    const float b30 = __ldg(&b3[0]);
    const float b31 = __ldg(&b3[1]);

    for (int c = blockIdx.x; c < NCHUNK; c += TBLK) {
        const int pbase = c * 16;            // 16 pairs; all < 2*QQ by range
        const int qbase = c * 8 + half * 4;  // this half's 4 q's

        // ---- layer 1: 4 q's x {resp=0,1} -> 8 h rows for this half ----
#pragma unroll
        for (int g = 0; g < 4; ++g) {
            int q = qbase + g;
            float td = fmaf(__expf(0.5f * __ldg(&dlv[q])), __ldg(&ed[q]), __ldg(&dmu[q]));
            float tc = fmaf(__expf(0.5f * __ldg(&clv[q])), __ldg(&ec[q]), __ldg(&cmu[q]));
            float pre0 = fmaf(td, w1a, fmaf(tc, w1b, b1j));   // resp = 0
            float pre1 = pre0 + w1c;                          // resp = 1
            h1s[half*8 + 2*g + 0][j] = gelu_exact(pre0);
            h1s[half*8 + 2*g + 1][j] = gelu_exact(pre1);
        }
        __syncthreads();

        // ---- layer 2: one W2 pass feeds 8 accumulators ----
        float acc[8];
#pragma unroll
        for (int p = 0; p < 8; ++p) acc[p] = b2j;
#pragma unroll 4
        for (int kc = 0; kc < 32; ++kc) {
            int k = kc * 4;
            float w0 = __ldg(&W2[(k+0)*HH + j]);
            float w1 = __ldg(&W2[(k+1)*HH + j]);
            float w2 = __ldg(&W2[(k+2)*HH + j]);
            float w3 = __ldg(&W2[(k+3)*HH + j]);
#pragma unroll
            for (int p = 0; p < 8; ++p) {
                float4 v = *reinterpret_cast<const float4*>(&h1s[half*8 + p][k]);
                acc[p] = fmaf(v.x, w0, fmaf(v.y, w1, fmaf(v.z, w2, fmaf(v.w, w3, acc[p]))));
            }
        }

        // ---- layer 3: 16 values per lane (8 pairs x {m0,m1}) ----
        float val[16];
#pragma unroll
        for (int p = 0; p < 8; ++p) {
            float hv = gelu_exact(acc[p]);
            val[2*p + 0] = hv * w3a;
            val[2*p + 1] = hv * w3b;
        }
        // Multi-value butterfly: stages o=16,8,4,2 halve the value count
        // (keep-half/exchange-half); after them lane L owns value (L>>1)&15;
        // stage o=1 completes the 32-lane sum. 15 shuffles total.
        {
            bool b16 = (lane & 16) != 0;
#pragma unroll
            for (int i = 0; i < 8; ++i) {
                float send = b16 ? val[i] : val[8+i];
                float r = __shfl_xor_sync(0xffffffffu, send, 16);
                val[i] = (b16 ? val[8+i] : val[i]) + r;
            }
            bool b8 = (lane & 8) != 0;
#pragma unroll
            for (int i = 0; i < 4; ++i) {
                float send = b8 ? val[i] : val[4+i];
                float r = __shfl_xor_sync(0xffffffffu, send, 8);
                val[i] = (b8 ? val[4+i] : val[i]) + r;
            }
            bool b4 = (lane & 4) != 0;
#pragma unroll
            for (int i = 0; i < 2; ++i) {
                float send = b4 ? val[i] : val[2+i];
                float r = __shfl_xor_sync(0xffffffffu, send, 4);
                val[i] = (b4 ? val[2+i] : val[i]) + r;
            }
            bool b2v = (lane & 2) != 0;
            {
                float send = b2v ? val[0] : val[1];
                float r = __shfl_xor_sync(0xffffffffu, send, 2);
                val[0] = (b2v ? val[1] : val[0]) + r;
            }
            val[0] += __shfl_xor_sync(0xffffffffu, val[0], 1);
        }
        if ((lane & 1) == 0) {
            int v = (lane >> 1) & 15;       // owned value index: p*2 + comp
            s_red[half*8 + (v >> 1)][v & 1][wwarp] = val[0];
        }
        __syncthreads();

        if (tid < 16) {                     // one thread finalizes each pair
            int pair = pbase + tid;
            float mu = b30 + ((s_red[tid][0][0] + s_red[tid][0][1])
                            + (s_red[tid][0][2] + s_red[tid][0][3]));
            float p1 = b31 + ((s_red[tid][1][0] + s_red[tid][1][1])
                            + (s_red[tid][1][2] + s_red[tid][1][3]));
            g_tab[pair] = make_float2(mu, fminf(__expf(-p1), 1e32f));
        }
        __syncthreads();
    }
}

// ---------------------------------------------------------------------------
// Kernel 2 (fused): per-user backward + forward scans via chunked warp scans.
// One warp per user (4 users / 128-thread block); lane k owns t in [16k,16k+16).
// Backward step matrix (homogeneous (p,q,w), a=p/q, ab=a*b=w/q):
//   [[1,l,0],[1,1+l,0],[0,lm,1]]; forgetting factor WC multiplies the older
//   composite's w-row during composition.
// KEY FUSION: the forward affine coefficients at step t are
//   inv = 1/(1+l+a_pre)  and  bet = (lm+ab_pre)*inv + sqrt(1-a_pre)*e,
// and the backward replay update uses the SAME reciprocal and the SAME
// product: ab_new = (lm+ab_pre)*inv. So the backward replay emits (inv, bet)
// directly — no an/abn arrays, one division per step instead of two.
// ---------------------------------------------------------------------------
__global__ void fused_scan_kernel(
        const int*   __restrict__ mask,
        const int*   __restrict__ q_id,
        const float* __restrict__ resp,
        const float* __restrict__ eps_ab,
        float*       __restrict__ out) {
    const int u = blockIdx.x * 4 + (threadIdx.x >> 5);
    const int k = threadIdx.x & 31;
    const int base = u * TT + k * CH;

    int4   mk4[4], q4[4];
    float4 r4[4], e4[4];
#pragma unroll
    for (int i = 0; i < 4; ++i) {
        mk4[i] = reinterpret_cast<const int4*>(mask + base)[i];
        q4[i]  = reinterpret_cast<const int4*>(q_id + base)[i];
        r4[i]  = reinterpret_cast<const float4*>(resp + base)[i];
        e4[i]  = reinterpret_cast<const float4*>(eps_ab + base)[i];
    }
    const int*   mk = reinterpret_cast<const int*>(mk4);
    const int*   qq = reinterpret_cast<const int*>(q4);
    const float* rr = reinterpret_cast<const float*>(r4);
    const float* ee = reinterpret_cast<const float*>(e4);

    float l[CH], lm[CH];
    bool  up[CH];
#pragma unroll
    for (int i = 0; i < CH; ++i) {
        int q = qq[i];
        int r = (rr[i] > 0.5f) ? 1 : 0;
        float2 ml = g_tab[(q << 1) | r];
        l[i]  = ml.y;
        lm[i] = ml.y * ml.x;
        up[i] = (mk[i] != 0);
    }

    // ---- backward: per-lane chunk matrix ----
    float A11 = 1.f, A12 = 0.f, A21 = 0.f, A22 = 1.f;
    float C1 = 0.f, C2 = 0.f, WC = 1.f;
#pragma unroll
    for (int i = CH - 1; i >= 0; --i) {
        if (up[i]) {
            float li = l[i];
            float s  = __fdividef(1.0f, 1.0f + li);
            float n11 = (A11 + li * A21) * s;
            float n12 = (A12 + li * A22) * s;
            float n21 = n11 + A21 * s;
            float n22 = n12 + A22 * s;
            float nc1 = fmaf(lm[i], A21, C1) * s;
            float nc2 = fmaf(lm[i], A22, C2) * s;
            A11 = n11; A12 = n12; A21 = n21; A22 = n22;
            C1 = nc1; C2 = nc2; WC *= s;
        }
    }
    {
        float s = __fdividef(1.0f, A22);
        A11 *= s; A12 *= s; A21 *= s; A22 *= s;
        C1 *= s; C2 *= s; WC *= s;
    }

    // ---- warp suffix scan (Z = A*Y; w-row: zc = C*y + WC*yc) ----
#pragma unroll
    for (int off = 1; off < 32; off <<= 1) {
        float y11 = __shfl_down_sync(0xffffffffu, A11, off);
        float y12 = __shfl_down_sync(0xffffffffu, A12, off);
        float y21 = __shfl_down_sync(0xffffffffu, A21, off);
        float y22 = __shfl_down_sync(0xffffffffu, A22, off);
        float yc1 = __shfl_down_sync(0xffffffffu, C1,  off);
        float yc2 = __shfl_down_sync(0xffffffffu, C2,  off);
        float ywc = __shfl_down_sync(0xffffffffu, WC,  off);
        if (k + off < 32) {
            float z11 = fmaf(A11, y11, A12 * y21);
            float z12 = fmaf(A11, y12, A12 * y22);
            float z21 = fmaf(A21, y11, A22 * y21);
            float z22 = fmaf(A21, y12, A22 * y22);
            float zc1 = fmaf(C1, y11, fmaf(C2, y21, WC * yc1));
            float zc2 = fmaf(C1, y12, fmaf(C2, y22, WC * yc2));
            float zwc = WC * ywc;
            float s = __fdividef(1.0f, z22);
            A11 = z11 * s; A12 = z12 * s; A21 = z21 * s; A22 = z22 * s;
            C1 = zc1 * s;  C2 = zc2 * s;  WC = zwc * s;
        }
    }
    float E12 = __shfl_down_sync(0xffffffffu, A12, 1);
    float E22 = __shfl_down_sync(0xffffffffu, A22, 1);
    float Ec2 = __shfl_down_sync(0xffffffffu, C2,  1);
    if (k == 31) { E12 = 0.f; E22 = 1.f; Ec2 = 0.f; }
    float a  = E12 / E22;
    float ab = Ec2 / E22;

    // ---- backward replay, emitting forward coefficients directly ----
    float inv[CH], bet[CH];
#pragma unroll
    for (int i = CH - 1; i >= 0; --i) {
        if (up[i]) {
            float d   = l[i] + a;
            float iv  = __fdividef(1.0f, 1.0f + d);
            float nab = (lm[i] + ab) * iv;         // == g of the forward step
            inv[i] = iv;
            bet[i] = fmaf(sqrtf(fmaxf(0.0f, 1.0f - a)), ee[i], nab);
            a  = d * iv;
            ab = nab;
        } else {
            inv[i] = 1.0f; bet[i] = 0.0f;
        }
    }

    // ---- per-lane affine compose (t ascending) ----
    float alC = 1.f, beC = 0.f;
#pragma unroll
    for (int i = 0; i < CH; ++i) {
        beC = fmaf(inv[i], beC, bet[i]);
        alC *= inv[i];
    }

    // ---- warp prefix scan of affine pairs ----
#pragma unroll
    for (int off = 1; off < 32; off <<= 1) {
        float ya = __shfl_up_sync(0xffffffffu, alC, off);
        float yb = __shfl_up_sync(0xffffffffu, beC, off);
        if (k >= off) {
            beC = fmaf(alC, yb, beC);
            alC *= ya;
        }
    }
    float th = __shfl_up_sync(0xffffffffu, beC, 1);
    if (k == 0) th = 0.f;

    // ---- forward replay + streaming float4 outputs ----
#pragma unroll
    for (int g = 0; g < 4; ++g) {
        float4 lof, aof;
#pragma unroll
        for (int s = 0; s < 4; ++s) {
            int i = 4*g + s;
            th = fmaf(th, inv[i], bet[i]);     // identity when masked
            int q = qq[i];
            float dc = g_disc[q];
            float lv = dc * (th - g_diff[q]);
            if (s == 0) { lof.x = lv; aof.x = th; }
            else if (s == 1) { lof.y = lv; aof.y = th; }
            else if (s == 2) { lof.z = lv; aof.z = th; }
            else { lof.w = lv; aof.w = th; }
        }
        reinterpret_cast<float4*>(out + base)[g] = lof;
        reinterpret_cast<float4*>(out + UT + base)[g] = aof;
    }
}

// ---------------------------------------------------------------------------
// Launch
// ---------------------------------------------------------------------------
extern "C" void kernel_launch(void* const* d_in, const int* in_sizes, int n_in,
                              void* d_out, int out_size) {
    const int*   mask   = (const int*)  d_in[0];
    const int*   q_id   = (const int*)  d_in[1];
    const float* resp   = (const float*)d_in[2];
    const float* dmu    = (const float*)d_in[3];
    const float* dlv    = (const float*)d_in[4];
    const float* cmu    = (const float*)d_in[5];
    const float* clv    = (const float*)d_in[6];
    const float* W1     = (const float*)d_in[7];
    const float* b1     = (const float*)d_in[8];
    const float* W2     = (const float*)d_in[9];
    const float* b2     = (const float*)d_in[10];
    const float* W3     = (const float*)d_in[11];
    const float* b3     = (const float*)d_in[12];
    const float* ed     = (const float*)d_in[13];
    const float* ec     = (const float*)d_in[14];
    const float* eps_ab = (const float*)d_in[15];
    float* out = (float*)d_out;

    table_kernel<<<TBLK, 256>>>(dmu, dlv, cmu, clv, ed, ec,
                                W1, b1, W2, b2, W3, b3);
    fused_scan_kernel<<<UU / 4, 128>>>(mask, q_id, resp, eps_ab, out);
}